// round 4
// baseline (speedup 1.0000x reference)
#include <cuda_runtime.h>
#include <math.h>

// ---------------------------------------------------------------------------
// Problem constants
// ---------------------------------------------------------------------------
#define D_LAYERS 2
#define C 1024
#define NH 16
#define KD 64
#define HS 14
#define NPATCH (HS*HS)          // 196
#define HID 4096
#define BATCH 32
#define M_ROWS (BATCH*NPATCH)   // 6272
#define SCALE_K 0.125f          // KD^-0.5

// ---------------------------------------------------------------------------
// Scratch buffers (static device globals; allocation-free rule)
// ---------------------------------------------------------------------------
__device__ float g_patch[M_ROWS*C];
__device__ float g_xn   [M_ROWS*C];
__device__ float g_q    [M_ROWS*C];
__device__ float g_k    [M_ROWS*C];
__device__ float g_v    [M_ROWS*C];
__device__ float g_att  [M_ROWS*C];
__device__ float g_hid  [M_ROWS*HID];
__device__ float g_sin  [NPATCH*KD];
__device__ float g_cos  [NPATCH*KD];

// ---------------------------------------------------------------------------
// RoPE-like table init: angle[d] = 10000^{-(d/2)/31}, sin/cos(pos*angle)
// ---------------------------------------------------------------------------
__global__ void rope_init_kernel() {
    int idx = blockIdx.x*blockDim.x + threadIdx.x;
    if (idx >= NPATCH*KD) return;
    int pos = idx >> 6;
    int d   = idx & 63;
    float t = (float)(d >> 1) / 31.0f;
    float ang = powf(10000.0f, -t);
    float a = (float)pos * ang;
    g_sin[idx] = sinf(a);
    g_cos[idx] = cosf(a);
}

// ---------------------------------------------------------------------------
// Extract patch tokens (drop cls) into g_patch
// ---------------------------------------------------------------------------
__global__ void copy_in_kernel(const float* __restrict__ x) {
    int idx = blockIdx.x*blockDim.x + threadIdx.x;
    if (idx >= M_ROWS*C) return;
    int m = idx >> 10;
    int c = idx & 1023;
    int b = m / NPATCH;
    int p = m % NPATCH;
    g_patch[idx] = x[((size_t)b*(NPATCH+1) + 1 + p)*C + c];
}

// ---------------------------------------------------------------------------
// Final write: cls token passthrough + patch tokens
// ---------------------------------------------------------------------------
__global__ void write_out_kernel(const float* __restrict__ x, float* __restrict__ out) {
    int idx = blockIdx.x*blockDim.x + threadIdx.x;
    if (idx >= BATCH*(NPATCH+1)*C) return;
    int row = idx >> 10;
    int c   = idx & 1023;
    int b = row / (NPATCH+1);
    int r = row % (NPATCH+1);
    out[idx] = (r == 0) ? x[idx] : g_patch[((size_t)(b*NPATCH + r - 1))*C + c];
}

// ---------------------------------------------------------------------------
// LayerNorm over C=1024, one block per row.
// ---------------------------------------------------------------------------
__global__ __launch_bounds__(256) void ln_kernel(const float* __restrict__ src,
                                                 const float* __restrict__ w,
                                                 const float* __restrict__ b,
                                                 float* __restrict__ dst) {
    __shared__ float row[C];
    __shared__ float red[256];
    int r = blockIdx.x;
    const float* xr = src + (size_t)r*C;
    float s = 0.f;
    for (int c = threadIdx.x; c < C; c += 256) { float v = xr[c]; row[c] = v; s += v; }
    red[threadIdx.x] = s; __syncthreads();
    for (int off = 128; off > 0; off >>= 1) {
        if (threadIdx.x < off) red[threadIdx.x] += red[threadIdx.x+off];
        __syncthreads();
    }
    float mean = red[0] * (1.0f/C);
    __syncthreads();
    float s2 = 0.f;
    for (int c = threadIdx.x; c < C; c += 256) { float d = row[c]-mean; s2 += d*d; }
    red[threadIdx.x] = s2; __syncthreads();
    for (int off = 128; off > 0; off >>= 1) {
        if (threadIdx.x < off) red[threadIdx.x] += red[threadIdx.x+off];
        __syncthreads();
    }
    float rstd = rsqrtf(red[0]*(1.0f/C) + 1e-5f);
    for (int c = threadIdx.x; c < C; c += 256)
        dst[(size_t)r*C + c] = (row[c]-mean)*rstd*w[c] + b[c];
}

// ---------------------------------------------------------------------------
// SGEMM: out[M,N] = (A[M,K] . W[N,K]^T + bias[N]) * scale  (+ add[M,N])
// 128x128 block tile, 8x8 micro-tile, BK=8.  Dims assumed multiples of tiles.
// ---------------------------------------------------------------------------
#define BM 128
#define BN 128
#define BK 8
__global__ __launch_bounds__(256) void sgemm_kernel(const float* __restrict__ A,
                                                    const float* __restrict__ W,
                                                    const float* __restrict__ bias,
                                                    const float* __restrict__ add,
                                                    float* __restrict__ out,
                                                    int M, int N, int K, float scale) {
    __shared__ float As[BK][BM];
    __shared__ float Bs[BK][BN];
    int tid = threadIdx.x;
    int tx = tid & 15;      // 0..15 -> N
    int ty = tid >> 4;      // 0..15 -> M
    int brow = blockIdx.y * BM;
    int bcol = blockIdx.x * BN;
    int lr = tid >> 1;            // 0..127
    int lc = (tid & 1) * 4;       // 0 or 4
    const float* Aptr = A + (size_t)(brow + lr)*K + lc;
    const float* Wptr = W + (size_t)(bcol + lr)*K + lc;
    float acc[8][8];
    #pragma unroll
    for (int i = 0; i < 8; i++)
        #pragma unroll
        for (int j = 0; j < 8; j++) acc[i][j] = 0.f;

    for (int kt = 0; kt < K; kt += BK) {
        float4 av = *(const float4*)(Aptr + kt);
        float4 wv = *(const float4*)(Wptr + kt);
        As[lc+0][lr]=av.x; As[lc+1][lr]=av.y; As[lc+2][lr]=av.z; As[lc+3][lr]=av.w;
        Bs[lc+0][lr]=wv.x; Bs[lc+1][lr]=wv.y; Bs[lc+2][lr]=wv.z; Bs[lc+3][lr]=wv.w;
        __syncthreads();
        #pragma unroll
        for (int kk = 0; kk < BK; kk++) {
            float4 a0 = *(const float4*)&As[kk][ty*8];
            float4 a1 = *(const float4*)&As[kk][ty*8+4];
            float4 b0 = *(const float4*)&Bs[kk][tx*8];
            float4 b1 = *(const float4*)&Bs[kk][tx*8+4];
            float ra[8] = {a0.x,a0.y,a0.z,a0.w,a1.x,a1.y,a1.z,a1.w};
            float rb[8] = {b0.x,b0.y,b0.z,b0.w,b1.x,b1.y,b1.z,b1.w};
            #pragma unroll
            for (int i = 0; i < 8; i++)
                #pragma unroll
                for (int j = 0; j < 8; j++)
                    acc[i][j] = fmaf(ra[i], rb[j], acc[i][j]);
        }
        __syncthreads();
    }
    #pragma unroll
    for (int i = 0; i < 8; i++) {
        int m = brow + ty*8 + i;
        #pragma unroll
        for (int j = 0; j < 8; j++) {
            int n = bcol + tx*8 + j;
            float v = (acc[i][j] + bias[n]) * scale;
            if (add) v += add[(size_t)m*N + n];
            out[(size_t)m*N + n] = v;
        }
    }
}

// ---------------------------------------------------------------------------
// Theta shift (in place, q AND k in one launch):
//   x = x*cos + rot2(x)*sin per even/odd pair within each head's 64 channels
// ---------------------------------------------------------------------------
__global__ void theta_shift_kernel(float* __restrict__ q, float* __restrict__ k) {
    int idx = blockIdx.x*blockDim.x + threadIdx.x;   // over M_ROWS*512 pairs
    if (idx >= M_ROWS*(C/2)) return;
    int m  = idx >> 9;          // /512
    int p  = idx & 511;
    int c0 = p*2;
    int d0 = c0 & 63;
    int pos = m % NPATCH;
    size_t base = (size_t)m*C + c0;
    float s0 = g_sin[pos*KD + d0],   cv0 = g_cos[pos*KD + d0];
    float s1 = g_sin[pos*KD + d0+1], cv1 = g_cos[pos*KD + d0+1];
    float q1 = q[base], q2 = q[base+1];
    q[base]   = q1*cv0 - q2*s0;
    q[base+1] = q2*cv1 + q1*s1;
    float k1 = k[base], k2 = k[base+1];
    k[base]   = k1*cv0 - k2*s0;
    k[base+1] = k2*cv1 + k1*s1;
}

// ---------------------------------------------------------------------------
// Axial attention, pass 1 (along width within each row).
// Block = (b, head n, row h).  Output layout identical to v: [b,h,w, n*64+d].
// ---------------------------------------------------------------------------
__global__ __launch_bounds__(256) void attn_w_kernel(const float* __restrict__ q,
                                                     const float* __restrict__ k,
                                                     const float* __restrict__ v,
                                                     float* __restrict__ out) {
    int bid = blockIdx.x;
    int h = bid % HS;
    int n = (bid / HS) % NH;
    int b = bid / (HS*NH);
    __shared__ float qs[HS][KD], ks[HS][KD], vs[HS][KD];
    __shared__ float sc[HS][HS];
    int baserow = b*NPATCH + h*HS;
    int col = n*KD;
    for (int t = threadIdx.x; t < HS*KD; t += 256) {
        int w = t >> 6, d = t & 63;
        size_t off = (size_t)(baserow + w)*C + col + d;
        qs[w][d] = q[off]; ks[w][d] = k[off]; vs[w][d] = v[off];
    }
    __syncthreads();
    float decay = logf(1.0f - exp2f(-1.0f - (float)n));
    for (int t = threadIdx.x; t < HS*HS; t += 256) {
        int w = t / HS, u = t % HS;
        float s = 0.f;
        #pragma unroll
        for (int d = 0; d < KD; d++) s = fmaf(qs[w][d], ks[u][d], s);
        sc[w][u] = s + fabsf((float)(w-u)) * decay;
    }
    __syncthreads();
    if (threadIdx.x < HS) {
        int w = threadIdx.x;
        float mx = -1e30f;
        for (int u = 0; u < HS; u++) mx = fmaxf(mx, sc[w][u]);
        float sum = 0.f, e[HS];
        for (int u = 0; u < HS; u++) { e[u] = __expf(sc[w][u]-mx); sum += e[u]; }
        float inv = 1.0f/sum;
        for (int u = 0; u < HS; u++) sc[w][u] = e[u]*inv;
    }
    __syncthreads();
    for (int t = threadIdx.x; t < HS*KD; t += 256) {
        int w = t >> 6, d = t & 63;
        float o = 0.f;
        #pragma unroll
        for (int u = 0; u < HS; u++) o = fmaf(sc[w][u], vs[u][d], o);
        out[(size_t)(baserow + w)*C + col + d] = o;
    }
}

// ---------------------------------------------------------------------------
// Axial attention, pass 2 (along height within each column).
// Block = (b, head n, column w). Values = pass-1 output. Output std layout.
// ---------------------------------------------------------------------------
__global__ __launch_bounds__(256) void attn_h_kernel(const float* __restrict__ q,
                                                     const float* __restrict__ k,
                                                     const float* __restrict__ v,
                                                     float* __restrict__ out) {
    int bid = blockIdx.x;
    int w = bid % HS;
    int n = (bid / HS) % NH;
    int b = bid / (HS*NH);
    __shared__ float qs[HS][KD], ks[HS][KD], vs[HS][KD];
    __shared__ float sc[HS][HS];
    int col = n*KD;
    for (int t = threadIdx.x; t < HS*KD; t += 256) {
        int hh = t >> 6, d = t & 63;
        size_t off = (size_t)(b*NPATCH + hh*HS + w)*C + col + d;
        qs[hh][d] = q[off]; ks[hh][d] = k[off]; vs[hh][d] = v[off];
    }
    __syncthreads();
    float decay = logf(1.0f - exp2f(-1.0f - (float)n));
    for (int t = threadIdx.x; t < HS*HS; t += 256) {
        int hh = t / HS, u = t % HS;
        float s = 0.f;
        #pragma unroll
        for (int d = 0; d < KD; d++) s = fmaf(qs[hh][d], ks[u][d], s);
        sc[hh][u] = s + fabsf((float)(hh-u)) * decay;
    }
    __syncthreads();
    if (threadIdx.x < HS) {
        int hh = threadIdx.x;
        float mx = -1e30f;
        for (int u = 0; u < HS; u++) mx = fmaxf(mx, sc[hh][u]);
        float sum = 0.f, e[HS];
        for (int u = 0; u < HS; u++) { e[u] = __expf(sc[hh][u]-mx); sum += e[u]; }
        float inv = 1.0f/sum;
        for (int u = 0; u < HS; u++) sc[hh][u] = e[u]*inv;
    }
    __syncthreads();
    for (int t = threadIdx.x; t < HS*KD; t += 256) {
        int hh = t >> 6, d = t & 63;
        float o = 0.f;
        #pragma unroll
        for (int u = 0; u < HS; u++) o = fmaf(sc[hh][u], vs[u][d], o);
        out[(size_t)(b*NPATCH + hh*HS + w)*C + col + d] = o;
    }
}

// ---------------------------------------------------------------------------
// LePE: depthwise 5x5 conv on v (pad 2) + bias, ACCUMULATED into out.
// ---------------------------------------------------------------------------
__global__ void lepe_kernel(const float* __restrict__ v,
                            const float* __restrict__ wgt,
                            const float* __restrict__ bias,
                            float* __restrict__ out) {
    int idx = blockIdx.x*blockDim.x + threadIdx.x;
    if (idx >= M_ROWS*C) return;
    int c = idx & 1023;
    int m = idx >> 10;
    int b = m / NPATCH;
    int p = m % NPATCH;
    int h = p / HS, w0 = p % HS;
    float acc = bias[c];
    #pragma unroll
    for (int kh = 0; kh < 5; kh++) {
        int hh = h + kh - 2;
        if (hh < 0 || hh >= HS) continue;
        #pragma unroll
        for (int kw = 0; kw < 5; kw++) {
            int ww = w0 + kw - 2;
            if (ww < 0 || ww >= HS) continue;
            acc = fmaf(v[(size_t)(b*NPATCH + hh*HS + ww)*C + c],
                       wgt[(kh*5+kw)*C + c], acc);
        }
    }
    out[idx] += acc;
}

// ---------------------------------------------------------------------------
// DyT: x = tanh(alpha*x)*w + b  (in place on g_hid)
// ---------------------------------------------------------------------------
__global__ void dyt_kernel(float* __restrict__ hbuf,
                           const float* __restrict__ alpha,
                           const float* __restrict__ w,
                           const float* __restrict__ b) {
    int idx = blockIdx.x*blockDim.x + threadIdx.x;
    if (idx >= M_ROWS*HID) return;
    int c = idx & 4095;
    hbuf[idx] = tanhf(alpha[0]*hbuf[idx])*w[c] + b[c];
}

// ---------------------------------------------------------------------------
// Launch
// ---------------------------------------------------------------------------
extern "C" void kernel_launch(void* const* d_in, const int* in_sizes, int n_in,
                              void* d_out, int out_size) {
    const float* x      = (const float*)d_in[0];
    const float* ln1_w  = (const float*)d_in[1];
    const float* ln1_b  = (const float*)d_in[2];
    const float* q_w    = (const float*)d_in[3];
    const float* q_b    = (const float*)d_in[4];
    const float* k_w    = (const float*)d_in[5];
    const float* k_b    = (const float*)d_in[6];
    const float* v_w    = (const float*)d_in[7];
    const float* v_b    = (const float*)d_in[8];
    const float* lepe_w = (const float*)d_in[9];
    const float* lepe_b = (const float*)d_in[10];
    const float* out_w  = (const float*)d_in[11];
    const float* out_b  = (const float*)d_in[12];
    const float* ln2_w  = (const float*)d_in[13];
    const float* ln2_b  = (const float*)d_in[14];
    const float* fc1_w  = (const float*)d_in[15];
    const float* fc1_b  = (const float*)d_in[16];
    const float* alpha  = (const float*)d_in[17];
    const float* dyt_w  = (const float*)d_in[18];
    const float* dyt_b  = (const float*)d_in[19];
    const float* fc2_w  = (const float*)d_in[20];
    const float* fc2_b  = (const float*)d_in[21];
    float* out = (float*)d_out;

    float *patch, *xn, *qb, *kb, *vb, *att, *hid;
    cudaGetSymbolAddress((void**)&patch, g_patch);
    cudaGetSymbolAddress((void**)&xn,    g_xn);
    cudaGetSymbolAddress((void**)&qb,    g_q);
    cudaGetSymbolAddress((void**)&kb,    g_k);
    cudaGetSymbolAddress((void**)&vb,    g_v);
    cudaGetSymbolAddress((void**)&att,   g_att);
    cudaGetSymbolAddress((void**)&hid,   g_hid);

    rope_init_kernel<<<(NPATCH*KD+255)/256, 256>>>();
    copy_in_kernel<<<(M_ROWS*C+255)/256, 256>>>(x);

    dim3 gemm_qkv(C/BN, M_ROWS/BM);       // (8, 49)
    dim3 gemm_fc1(HID/BN, M_ROWS/BM);     // (32, 49)

    for (int d = 0; d < D_LAYERS; d++) {
        const float* l1w = ln1_w + d*C;   const float* l1b = ln1_b + d*C;
        const float* qw  = q_w  + (size_t)d*C*C;   const float* qbi = q_b  + d*C;
        const float* kw  = k_w  + (size_t)d*C*C;   const float* kbi = k_b  + d*C;
        const float* vw  = v_w  + (size_t)d*C*C;   const float* vbi = v_b  + d*C;
        const float* lw  = lepe_w + (size_t)d*25*C; const float* lb = lepe_b + d*C;
        const float* ow  = out_w + (size_t)d*C*C;  const float* obi = out_b + d*C;
        const float* l2w = ln2_w + d*C;   const float* l2b = ln2_b + d*C;
        const float* f1w = fc1_w + (size_t)d*HID*C; const float* f1b = fc1_b + d*HID;
        const float* al  = alpha + d;
        const float* dw  = dyt_w + d*HID; const float* db = dyt_b + d*HID;
        const float* f2w = fc2_w + (size_t)d*C*HID; const float* f2b = fc2_b + d*C;

        // --- attention half ---
        ln_kernel<<<M_ROWS, 256>>>(patch, l1w, l1b, xn);
        sgemm_kernel<<<gemm_qkv, 256>>>(xn, qw, qbi, nullptr, qb, M_ROWS, C, C, 1.0f);
        sgemm_kernel<<<gemm_qkv, 256>>>(xn, kw, kbi, nullptr, kb, M_ROWS, C, C, SCALE_K);
        sgemm_kernel<<<gemm_qkv, 256>>>(xn, vw, vbi, nullptr, vb, M_ROWS, C, C, 1.0f);
        theta_shift_kernel<<<(M_ROWS*(C/2)+255)/256, 256>>>(qb, kb);
        attn_w_kernel<<<BATCH*NH*HS, 256>>>(qb, kb, vb, att);
        attn_h_kernel<<<BATCH*NH*HS, 256>>>(qb, kb, att, xn);
        lepe_kernel<<<(M_ROWS*C+255)/256, 256>>>(vb, lw, lb, xn);
        // out projection + residual (accumulate into patch)
        sgemm_kernel<<<gemm_qkv, 256>>>(xn, ow, obi, patch, patch, M_ROWS, C, C, 1.0f);

        // --- MLP half ---
        ln_kernel<<<M_ROWS, 256>>>(patch, l2w, l2b, xn);
        sgemm_kernel<<<gemm_fc1, 256>>>(xn, f1w, f1b, nullptr, hid, M_ROWS, HID, C, 1.0f);
        dyt_kernel<<<(M_ROWS*HID+255)/256, 256>>>(hid, al, dw, db);
        sgemm_kernel<<<gemm_qkv, 256>>>(hid, f2w, f2b, patch, patch, M_ROWS, C, HID, 1.0f);
    }

    write_out_kernel<<<(BATCH*(NPATCH+1)*C+255)/256, 256>>>(x, out);
}

// round 10
// speedup vs baseline: 3.0370x; 3.0370x over previous
#include <cuda_runtime.h>
#include <cuda_bf16.h>
#include <mma.h>
#include <math.h>
#include <stdint.h>

using namespace nvcuda;

// ---------------------------------------------------------------------------
// Problem constants
// ---------------------------------------------------------------------------
#define D_LAYERS 2
#define C 1024
#define NH 16
#define KD 64
#define HS 14
#define NPATCH (HS*HS)          // 196
#define HID 4096
#define BATCH 32
#define M_ROWS (BATCH*NPATCH)   // 6272
#define SCALE_K 0.125f          // KD^-0.5

// ---------------------------------------------------------------------------
// Scratch buffers (static device globals; allocation-free rule)
// ---------------------------------------------------------------------------
__device__ float g_patch[M_ROWS*C];
__device__ float g_xn   [M_ROWS*C];
__device__ float g_q    [M_ROWS*C];
__device__ float g_k    [M_ROWS*C];
__device__ float g_v    [M_ROWS*C];
__device__ float g_hid  [M_ROWS*HID];
__device__ float g_sin  [NPATCH*KD];
__device__ float g_cos  [NPATCH*KD];
__device__ float g_att  [M_ROWS*C];
// bf16 hi/lo operand scratch for tensor-core GEMMs
__device__ __nv_bfloat16 g_ahi[M_ROWS*HID];
__device__ __nv_bfloat16 g_alo[M_ROWS*HID];
__device__ __nv_bfloat16 g_bhi[HID*C];
__device__ __nv_bfloat16 g_blo[HID*C];

__device__ __forceinline__ uint32_t smem_u32(const void* p) {
    uint32_t a;
    asm("{ .reg .u64 t; cvta.to.shared.u64 t, %1; cvt.u32.u64 %0, t; }" : "=r"(a) : "l"(p));
    return a;
}

// ---------------------------------------------------------------------------
// fp32 -> bf16 hi/lo split (vectorized by 4)
// ---------------------------------------------------------------------------
__global__ void cvt_split_kernel(const float4* __restrict__ x,
                                 __nv_bfloat162* __restrict__ hi,
                                 __nv_bfloat162* __restrict__ lo, int n4) {
    int i = blockIdx.x*blockDim.x + threadIdx.x;
    if (i >= n4) return;
    float4 v = x[i];
    __nv_bfloat16 h0 = __float2bfloat16(v.x);
    __nv_bfloat16 h1 = __float2bfloat16(v.y);
    __nv_bfloat16 h2 = __float2bfloat16(v.z);
    __nv_bfloat16 h3 = __float2bfloat16(v.w);
    hi[2*i+0] = __halves2bfloat162(h0, h1);
    hi[2*i+1] = __halves2bfloat162(h2, h3);
    lo[2*i+0] = __halves2bfloat162(__float2bfloat16(v.x - __bfloat162float(h0)),
                                   __float2bfloat16(v.y - __bfloat162float(h1)));
    lo[2*i+1] = __halves2bfloat162(__float2bfloat16(v.z - __bfloat162float(h2)),
                                   __float2bfloat16(v.w - __bfloat162float(h3)));
}

// ---------------------------------------------------------------------------
// wmma bf16-split GEMM:
//   out[M,N] = (sum_k A[M,K].B[N,K]^T + bias[N]) * scale (+ add[M,N])
//   A ~ Ahi+Alo, B ~ Bhi+Blo (bf16), fp32 accumulate.
// CTA tile 128x128, 8 warps (4 M x 2 N), warp tile 32x64, BK=32,
// cp.async 2-stage double buffer, padded smem rows (40 elements = 80B).
// ---------------------------------------------------------------------------
#define PAD 40
#define BKW 32
#define TILE_ELE (128*PAD)              // 5120 bf16 per operand tile
#define STAGE_ELE (4*TILE_ELE)          // 20480 bf16 per stage
#define GSM_BYTES (2*STAGE_ELE*2)       // 81920 bytes

__global__ __launch_bounds__(256, 1) void gemm_wmma_kernel(
        const __nv_bfloat16* __restrict__ Ahi, const __nv_bfloat16* __restrict__ Alo,
        const __nv_bfloat16* __restrict__ Bhi, const __nv_bfloat16* __restrict__ Blo,
        const float* __restrict__ bias, const float* add, float* __restrict__ out,
        int M, int N, int K, float scale) {
    extern __shared__ __nv_bfloat16 smb[];
    int tid = threadIdx.x, wid = tid >> 5;
    int brow = blockIdx.y * 128;
    int bcol = blockIdx.x * 128;
    int warp_m = wid & 3;        // 0..3  -> 32 rows each
    int warp_n = wid >> 2;       // 0..1  -> 64 cols each
    uint32_t smem_base = smem_u32(smb);

    wmma::fragment<wmma::accumulator,16,16,16,float> acc[2][4];
    #pragma unroll
    for (int i = 0; i < 2; i++)
        #pragma unroll
        for (int j = 0; j < 4; j++) wmma::fill_fragment(acc[i][j], 0.f);

    int nsteps = K / BKW;

    // stage loader: 4 operand tiles x 128 rows x 64B (4 x 16B chunks per row)
    auto load_stage = [&](int ks, int buf) {
        #pragma unroll
        for (int it = 0; it < 8; it++) {
            int t  = tid + it*256;            // 0..2047
            int op = t >> 9;                  // 0..3
            int r  = (t >> 2) & 127;
            int ch = t & 3;
            const __nv_bfloat16* g;
            if (op == 0)      g = Ahi + (size_t)(brow + r)*K + ks*BKW + ch*8;
            else if (op == 1) g = Alo + (size_t)(brow + r)*K + ks*BKW + ch*8;
            else if (op == 2) g = Bhi + (size_t)(bcol + r)*K + ks*BKW + ch*8;
            else              g = Blo + (size_t)(bcol + r)*K + ks*BKW + ch*8;
            uint32_t s = smem_base + (uint32_t)(buf*STAGE_ELE + op*TILE_ELE + r*PAD + ch*8)*2u;
            asm volatile("cp.async.cg.shared.global [%0], [%1], 16;" :: "r"(s), "l"(g));
        }
        asm volatile("cp.async.commit_group;");
    };

    load_stage(0, 0);
    for (int ks = 0; ks < nsteps; ks++) {
        asm volatile("cp.async.wait_group 0;");
        __syncthreads();
        if (ks + 1 < nsteps) load_stage(ks + 1, (ks + 1) & 1);

        const __nv_bfloat16* sA_hi = smb + (ks & 1)*STAGE_ELE;
        const __nv_bfloat16* sA_lo = sA_hi + TILE_ELE;
        const __nv_bfloat16* sB_hi = sA_hi + 2*TILE_ELE;
        const __nv_bfloat16* sB_lo = sA_hi + 3*TILE_ELE;

        #pragma unroll
        for (int kk = 0; kk < 2; kk++) {      // two k16 sub-steps
            wmma::fragment<wmma::matrix_a,16,16,16,__nv_bfloat16,wmma::row_major> ah[2], al[2];
            wmma::fragment<wmma::matrix_b,16,16,16,__nv_bfloat16,wmma::col_major> bh[4], bl[4];
            #pragma unroll
            for (int mi = 0; mi < 2; mi++) {
                int m0 = warp_m*32 + mi*16;
                wmma::load_matrix_sync(ah[mi], sA_hi + m0*PAD + kk*16, PAD);
                wmma::load_matrix_sync(al[mi], sA_lo + m0*PAD + kk*16, PAD);
            }
            #pragma unroll
            for (int ni = 0; ni < 4; ni++) {
                int n0 = warp_n*64 + ni*16;
                wmma::load_matrix_sync(bh[ni], sB_hi + n0*PAD + kk*16, PAD);
                wmma::load_matrix_sync(bl[ni], sB_lo + n0*PAD + kk*16, PAD);
            }
            #pragma unroll
            for (int mi = 0; mi < 2; mi++)
                #pragma unroll
                for (int ni = 0; ni < 4; ni++) {
                    wmma::mma_sync(acc[mi][ni], ah[mi], bh[ni], acc[mi][ni]);
                    wmma::mma_sync(acc[mi][ni], ah[mi], bl[ni], acc[mi][ni]);
                    wmma::mma_sync(acc[mi][ni], al[mi], bh[ni], acc[mi][ni]);
                }
        }
        __syncthreads();
    }

    // Epilogue: frags -> smem (float, stride 132) -> fused bias/scale/add -> gmem
    float* sep = (float*)smb;     // 128 x 132 floats = 67584B <= 81920B
    #pragma unroll
    for (int mi = 0; mi < 2; mi++)
        #pragma unroll
        for (int ni = 0; ni < 4; ni++)
            wmma::store_matrix_sync(sep + (warp_m*32 + mi*16)*132 + warp_n*64 + ni*16,
                                    acc[mi][ni], 132, wmma::mem_row_major);
    __syncthreads();
    for (int t = tid; t < 128*128; t += 256) {
        int r = t >> 7, c = t & 127;
        int m = brow + r, n = bcol + c;
        float v = (sep[r*132 + c] + bias[n]) * scale;
        if (add) v += add[(size_t)m*N + n];
        out[(size_t)m*N + n] = v;
    }
}

// ---------------------------------------------------------------------------
// RoPE-like table init
// ---------------------------------------------------------------------------
__global__ void rope_init_kernel() {
    int idx = blockIdx.x*blockDim.x + threadIdx.x;
    if (idx >= NPATCH*KD) return;
    int pos = idx >> 6;
    int d   = idx & 63;
    float t = (float)(d >> 1) / 31.0f;
    float ang = powf(10000.0f, -t);
    float a = (float)pos * ang;
    g_sin[idx] = sinf(a);
    g_cos[idx] = cosf(a);
}

__global__ void copy_in_kernel(const float* __restrict__ x) {
    int idx = blockIdx.x*blockDim.x + threadIdx.x;
    if (idx >= M_ROWS*C) return;
    int m = idx >> 10;
    int c = idx & 1023;
    int b = m / NPATCH;
    int p = m % NPATCH;
    g_patch[idx] = x[((size_t)b*(NPATCH+1) + 1 + p)*C + c];
}

__global__ void write_out_kernel(const float* __restrict__ x, float* __restrict__ out) {
    int idx = blockIdx.x*blockDim.x + threadIdx.x;
    if (idx >= BATCH*(NPATCH+1)*C) return;
    int row = idx >> 10;
    int c   = idx & 1023;
    int b = row / (NPATCH+1);
    int r = row % (NPATCH+1);
    out[idx] = (r == 0) ? x[idx] : g_patch[((size_t)(b*NPATCH + r - 1))*C + c];
}

// ---------------------------------------------------------------------------
// LayerNorm over C=1024, one block per row.
// ---------------------------------------------------------------------------
__global__ __launch_bounds__(256) void ln_kernel(const float* __restrict__ src,
                                                 const float* __restrict__ w,
                                                 const float* __restrict__ b,
                                                 float* __restrict__ dst) {
    __shared__ float row[C];
    __shared__ float red[256];
    int r = blockIdx.x;
    const float* xr = src + (size_t)r*C;
    float s = 0.f;
    for (int c = threadIdx.x; c < C; c += 256) { float v = xr[c]; row[c] = v; s += v; }
    red[threadIdx.x] = s; __syncthreads();
    for (int off = 128; off > 0; off >>= 1) {
        if (threadIdx.x < off) red[threadIdx.x] += red[threadIdx.x+off];
        __syncthreads();
    }
    float mean = red[0] * (1.0f/C);
    __syncthreads();
    float s2 = 0.f;
    for (int c = threadIdx.x; c < C; c += 256) { float d = row[c]-mean; s2 += d*d; }
    red[threadIdx.x] = s2; __syncthreads();
    for (int off = 128; off > 0; off >>= 1) {
        if (threadIdx.x < off) red[threadIdx.x] += red[threadIdx.x+off];
        __syncthreads();
    }
    float rstd = rsqrtf(red[0]*(1.0f/C) + 1e-5f);
    for (int c = threadIdx.x; c < C; c += 256)
        dst[(size_t)r*C + c] = (row[c]-mean)*rstd*w[c] + b[c];
}

// ---------------------------------------------------------------------------
// Theta shift (in place, q AND k)
// ---------------------------------------------------------------------------
__global__ void theta_shift_kernel(float* __restrict__ q, float* __restrict__ k) {
    int idx = blockIdx.x*blockDim.x + threadIdx.x;
    if (idx >= M_ROWS*(C/2)) return;
    int m  = idx >> 9;
    int p  = idx & 511;
    int c0 = p*2;
    int d0 = c0 & 63;
    int pos = m % NPATCH;
    size_t base = (size_t)m*C + c0;
    float s0 = g_sin[pos*KD + d0],   cv0 = g_cos[pos*KD + d0];
    float s1 = g_sin[pos*KD + d0+1], cv1 = g_cos[pos*KD + d0+1];
    float q1 = q[base], q2 = q[base+1];
    q[base]   = q1*cv0 - q2*s0;
    q[base+1] = q2*cv1 + q1*s1;
    float k1 = k[base], k2 = k[base+1];
    k[base]   = k1*cv0 - k2*s0;
    k[base+1] = k2*cv1 + k1*s1;
}

// ---------------------------------------------------------------------------
// Axial attention pass 1 (along width)
// ---------------------------------------------------------------------------
__global__ __launch_bounds__(256) void attn_w_kernel(const float* __restrict__ q,
                                                     const float* __restrict__ k,
                                                     const float* __restrict__ v,
                                                     float* __restrict__ out) {
    int bid = blockIdx.x;
    int h = bid % HS;
    int n = (bid / HS) % NH;
    int b = bid / (HS*NH);
    __shared__ float qs[HS][KD], ks[HS][KD], vs[HS][KD];
    __shared__ float sc[HS][HS];
    int baserow = b*NPATCH + h*HS;
    int col = n*KD;
    for (int t = threadIdx.x; t < HS*KD; t += 256) {
        int w = t >> 6, d = t & 63;
        size_t off = (size_t)(baserow + w)*C + col + d;
        qs[w][d] = q[off]; ks[w][d] = k[off]; vs[w][d] = v[off];
    }
    __syncthreads();
    float decay = logf(1.0f - exp2f(-1.0f - (float)n));
    for (int t = threadIdx.x; t < HS*HS; t += 256) {
        int w = t / HS, u = t % HS;
        float s = 0.f;
        #pragma unroll
        for (int d = 0; d < KD; d++) s = fmaf(qs[w][d], ks[u][d], s);
        sc[w][u] = s + fabsf((float)(w-u)) * decay;
    }
    __syncthreads();
    if (threadIdx.x < HS) {
        int w = threadIdx.x;
        float mx = -1e30f;
        for (int u = 0; u < HS; u++) mx = fmaxf(mx, sc[w][u]);
        float sum = 0.f, e[HS];
        for (int u = 0; u < HS; u++) { e[u] = __expf(sc[w][u]-mx); sum += e[u]; }
        float inv = 1.0f/sum;
        for (int u = 0; u < HS; u++) sc[w][u] = e[u]*inv;
    }
    __syncthreads();
    for (int t = threadIdx.x; t < HS*KD; t += 256) {
        int w = t >> 6, d = t & 63;
        float o = 0.f;
        #pragma unroll
        for (int u = 0; u < HS; u++) o = fmaf(sc[w][u], vs[u][d], o);
        out[(size_t)(baserow + w)*C + col + d] = o;
    }
}

// ---------------------------------------------------------------------------
// Axial attention pass 2 (along height)
// ---------------------------------------------------------------------------
__global__ __launch_bounds__(256) void attn_h_kernel(const float* __restrict__ q,
                                                     const float* __restrict__ k,
                                                     const float* __restrict__ v,
                                                     float* __restrict__ out) {
    int bid = blockIdx.x;
    int w = bid % HS;
    int n = (bid / HS) % NH;
    int b = bid / (HS*NH);
    __shared__ float qs[HS][KD], ks[HS][KD], vs[HS][KD];
    __shared__ float sc[HS][HS];
    int col = n*KD;
    for (int t = threadIdx.x; t < HS*KD; t += 256) {
        int hh = t >> 6, d = t & 63;
        size_t off = (size_t)(b*NPATCH + hh*HS + w)*C + col + d;
        qs[hh][d] = q[off]; ks[hh][d] = k[off]; vs[hh][d] = v[off];
    }
    __syncthreads();
    float decay = logf(1.0f - exp2f(-1.0f - (float)n));
    for (int t = threadIdx.x; t < HS*HS; t += 256) {
        int hh = t / HS, u = t % HS;
        float s = 0.f;
        #pragma unroll
        for (int d = 0; d < KD; d++) s = fmaf(qs[hh][d], ks[u][d], s);
        sc[hh][u] = s + fabsf((float)(hh-u)) * decay;
    }
    __syncthreads();
    if (threadIdx.x < HS) {
        int hh = threadIdx.x;
        float mx = -1e30f;
        for (int u = 0; u < HS; u++) mx = fmaxf(mx, sc[hh][u]);
        float sum = 0.f, e[HS];
        for (int u = 0; u < HS; u++) { e[u] = __expf(sc[hh][u]-mx); sum += e[u]; }
        float inv = 1.0f/sum;
        for (int u = 0; u < HS; u++) sc[hh][u] = e[u]*inv;
    }
    __syncthreads();
    for (int t = threadIdx.x; t < HS*KD; t += 256) {
        int hh = t >> 6, d = t & 63;
        float o = 0.f;
        #pragma unroll
        for (int u = 0; u < HS; u++) o = fmaf(sc[hh][u], vs[u][d], o);
        out[(size_t)(b*NPATCH + hh*HS + w)*C + col + d] = o;
    }
}

// ---------------------------------------------------------------------------
// LePE: depthwise 5x5 conv on v (pad 2) + bias, ACCUMULATED into out.
// ---------------------------------------------------------------------------
__global__ void lepe_kernel(const float* __restrict__ v,
                            const float* __restrict__ wgt,
                            const float* __restrict__ bias,
                            float* __restrict__ out) {
    int idx = blockIdx.x*blockDim.x + threadIdx.x;
    if (idx >= M_ROWS*C) return;
    int c = idx & 1023;
    int m = idx >> 10;
    int b = m / NPATCH;
    int p = m % NPATCH;
    int h = p / HS, w0 = p % HS;
    float acc = bias[c];
    #pragma unroll
    for (int kh = 0; kh < 5; kh++) {
        int hh = h + kh - 2;
        if (hh < 0 || hh >= HS) continue;
        #pragma unroll
        for (int kw = 0; kw < 5; kw++) {
            int ww = w0 + kw - 2;
            if (ww < 0 || ww >= HS) continue;
            acc = fmaf(v[(size_t)(b*NPATCH + hh*HS + ww)*C + c],
                       wgt[(kh*5+kw)*C + c], acc);
        }
    }
    out[idx] += acc;
}

// ---------------------------------------------------------------------------
// DyT: x = tanh(alpha*x)*w + b  (in place on g_hid)
// ---------------------------------------------------------------------------
__global__ void dyt_kernel(float* __restrict__ hbuf,
                           const float* __restrict__ alpha,
                           const float* __restrict__ w,
                           const float* __restrict__ b) {
    int idx = blockIdx.x*blockDim.x + threadIdx.x;
    if (idx >= M_ROWS*HID) return;
    int c = idx & 4095;
    hbuf[idx] = tanhf(alpha[0]*hbuf[idx])*w[c] + b[c];
}

// ---------------------------------------------------------------------------
// Launch
// ---------------------------------------------------------------------------
static void cvt(const float* src, __nv_bfloat16* hi, __nv_bfloat16* lo, int n) {
    int n4 = n / 4;
    cvt_split_kernel<<<(n4+255)/256, 256>>>((const float4*)src,
                                            (__nv_bfloat162*)hi, (__nv_bfloat162*)lo, n4);
}

extern "C" void kernel_launch(void* const* d_in, const int* in_sizes, int n_in,
                              void* d_out, int out_size) {
    const float* x      = (const float*)d_in[0];
    const float* ln1_w  = (const float*)d_in[1];
    const float* ln1_b  = (const float*)d_in[2];
    const float* q_w    = (const float*)d_in[3];
    const float* q_b    = (const float*)d_in[4];
    const float* k_w    = (const float*)d_in[5];
    const float* k_b    = (const float*)d_in[6];
    const float* v_w    = (const float*)d_in[7];
    const float* v_b    = (const float*)d_in[8];
    const float* lepe_w = (const float*)d_in[9];
    const float* lepe_b = (const float*)d_in[10];
    const float* out_w  = (const float*)d_in[11];
    const float* out_b  = (const float*)d_in[12];
    const float* ln2_w  = (const float*)d_in[13];
    const float* ln2_b  = (const float*)d_in[14];
    const float* fc1_w  = (const float*)d_in[15];
    const float* fc1_b  = (const float*)d_in[16];
    const float* alpha  = (const float*)d_in[17];
    const float* dyt_w  = (const float*)d_in[18];
    const float* dyt_b  = (const float*)d_in[19];
    const float* fc2_w  = (const float*)d_in[20];
    const float* fc2_b  = (const float*)d_in[21];
    float* out = (float*)d_out;

    float *patch, *xn, *qb, *kb, *vb, *att, *hid;
    __nv_bfloat16 *ahi, *alo, *bhi, *blo;
    cudaGetSymbolAddress((void**)&patch, g_patch);
    cudaGetSymbolAddress((void**)&xn,    g_xn);
    cudaGetSymbolAddress((void**)&qb,    g_q);
    cudaGetSymbolAddress((void**)&kb,    g_k);
    cudaGetSymbolAddress((void**)&vb,    g_v);
    cudaGetSymbolAddress((void**)&att,   g_att);
    cudaGetSymbolAddress((void**)&hid,   g_hid);
    cudaGetSymbolAddress((void**)&ahi,   g_ahi);
    cudaGetSymbolAddress((void**)&alo,   g_alo);
    cudaGetSymbolAddress((void**)&bhi,   g_bhi);
    cudaGetSymbolAddress((void**)&blo,   g_blo);

    cudaFuncSetAttribute(gemm_wmma_kernel, cudaFuncAttributeMaxDynamicSharedMemorySize, GSM_BYTES);

    rope_init_kernel<<<(NPATCH*KD+255)/256, 256>>>();
    copy_in_kernel<<<(M_ROWS*C+255)/256, 256>>>(x);

    dim3 gC(C/128,   M_ROWS/128);   // (8, 49)
    dim3 gH(HID/128, M_ROWS/128);   // (32, 49)

    for (int d = 0; d < D_LAYERS; d++) {
        const float* l1w = ln1_w + d*C;   const float* l1b = ln1_b + d*C;
        const float* qw  = q_w  + (size_t)d*C*C;   const float* qbi = q_b  + d*C;
        const float* kw  = k_w  + (size_t)d*C*C;   const float* kbi = k_b  + d*C;
        const float* vw  = v_w  + (size_t)d*C*C;   const float* vbi = v_b  + d*C;
        const float* lw  = lepe_w + (size_t)d*25*C; const float* lb = lepe_b + d*C;
        const float* ow  = out_w + (size_t)d*C*C;  const float* obi = out_b + d*C;
        const float* l2w = ln2_w + d*C;   const float* l2b = ln2_b + d*C;
        const float* f1w = fc1_w + (size_t)d*HID*C; const float* f1b = fc1_b + d*HID;
        const float* al  = alpha + d;
        const float* dw  = dyt_w + d*HID; const float* db = dyt_b + d*HID;
        const float* f2w = fc2_w + (size_t)d*C*HID; const float* f2b = fc2_b + d*C;

        // --- attention half ---
        ln_kernel<<<M_ROWS, 256>>>(patch, l1w, l1b, xn);
        cvt(xn, ahi, alo, M_ROWS*C);
        cvt(qw, bhi, blo, C*C);
        gemm_wmma_kernel<<<gC, 256, GSM_BYTES>>>(ahi, alo, bhi, blo, qbi, nullptr, qb, M_ROWS, C, C, 1.0f);
        cvt(kw, bhi, blo, C*C);
        gemm_wmma_kernel<<<gC, 256, GSM_BYTES>>>(ahi, alo, bhi, blo, kbi, nullptr, kb, M_ROWS, C, C, SCALE_K);
        cvt(vw, bhi, blo, C*C);
        gemm_wmma_kernel<<<gC, 256, GSM_BYTES>>>(ahi, alo, bhi, blo, vbi, nullptr, vb, M_ROWS, C, C, 1.0f);
        theta_shift_kernel<<<(M_ROWS*(C/2)+255)/256, 256>>>(qb, kb);
        attn_w_kernel<<<BATCH*NH*HS, 256>>>(qb, kb, vb, att);
        attn_h_kernel<<<BATCH*NH*HS, 256>>>(qb, kb, att, xn);
        lepe_kernel<<<(M_ROWS*C+255)/256, 256>>>(vb, lw, lb, xn);
        // out projection + residual (accumulate into patch)
        cvt(xn, ahi, alo, M_ROWS*C);
        cvt(ow, bhi, blo, C*C);
        gemm_wmma_kernel<<<gC, 256, GSM_BYTES>>>(ahi, alo, bhi, blo, obi, patch, patch, M_ROWS, C, C, 1.0f);

        // --- MLP half ---
        ln_kernel<<<M_ROWS, 256>>>(patch, l2w, l2b, xn);
        cvt(xn, ahi, alo, M_ROWS*C);
        cvt(f1w, bhi, blo, HID*C);
        gemm_wmma_kernel<<<gH, 256, GSM_BYTES>>>(ahi, alo, bhi, blo, f1b, nullptr, hid, M_ROWS, HID, C, 1.0f);
        dyt_kernel<<<(M_ROWS*HID+255)/256, 256>>>(hid, al, dw, db);
        cvt(hid, ahi, alo, M_ROWS*HID);
        cvt(f2w, bhi, blo, C*HID);
        gemm_wmma_kernel<<<gC, 256, GSM_BYTES>>>(ahi, alo, bhi, blo, f2b, patch, patch, M_ROWS, C, HID, 1.0f);
    }

    write_out_kernel<<<(BATCH*(NPATCH+1)*C+255)/256, 256>>>(x, out);
}

// round 11
// speedup vs baseline: 3.1252x; 1.0290x over previous
#include <cuda_runtime.h>
#include <cuda_bf16.h>
#include <mma.h>
#include <math.h>
#include <stdint.h>

using namespace nvcuda;

// ---------------------------------------------------------------------------
// Problem constants
// ---------------------------------------------------------------------------
#define D_LAYERS 2
#define C 1024
#define NH 16
#define KD 64
#define HS 14
#define NPATCH (HS*HS)          // 196
#define HID 4096
#define BATCH 32
#define M_ROWS (BATCH*NPATCH)   // 6272
#define SCALE_K 0.125f          // KD^-0.5

// ---------------------------------------------------------------------------
// Scratch buffers (static device globals; allocation-free rule)
// ---------------------------------------------------------------------------
__device__ float g_patch[M_ROWS*C];
__device__ float g_xn   [M_ROWS*C];
__device__ float g_q    [M_ROWS*C];
__device__ float g_k    [M_ROWS*C];
__device__ float g_v    [M_ROWS*C];
__device__ float g_hid  [M_ROWS*HID];
__device__ float g_sin  [NPATCH*KD];
__device__ float g_cos  [NPATCH*KD];
// bf16 hi/lo operand scratch for tensor-core GEMMs
__device__ __nv_bfloat16 g_ahi[M_ROWS*HID];
__device__ __nv_bfloat16 g_alo[M_ROWS*HID];
__device__ __nv_bfloat16 g_bhi[HID*C];
__device__ __nv_bfloat16 g_blo[HID*C];

__device__ __forceinline__ uint32_t smem_u32(const void* p) {
    uint32_t a;
    asm("{ .reg .u64 t; cvta.to.shared.u64 t, %1; cvt.u32.u64 %0, t; }" : "=r"(a) : "l"(p));
    return a;
}

__device__ __forceinline__ void split_bf(float v, __nv_bfloat16& h, __nv_bfloat16& l) {
    h = __float2bfloat16(v);
    l = __float2bfloat16(v - __bfloat162float(h));
}

// ---------------------------------------------------------------------------
// fp32 -> bf16 hi/lo split (vectorized by 4) — used for weights only
// ---------------------------------------------------------------------------
__global__ void cvt_split_kernel(const float4* __restrict__ x,
                                 __nv_bfloat162* __restrict__ hi,
                                 __nv_bfloat162* __restrict__ lo, int n4) {
    int i = blockIdx.x*blockDim.x + threadIdx.x;
    if (i >= n4) return;
    float4 v = x[i];
    __nv_bfloat16 h0, l0, h1, l1, h2, l2, h3, l3;
    split_bf(v.x, h0, l0); split_bf(v.y, h1, l1);
    split_bf(v.z, h2, l2); split_bf(v.w, h3, l3);
    hi[2*i+0] = __halves2bfloat162(h0, h1);
    hi[2*i+1] = __halves2bfloat162(h2, h3);
    lo[2*i+0] = __halves2bfloat162(l0, l1);
    lo[2*i+1] = __halves2bfloat162(l2, l3);
}

// ---------------------------------------------------------------------------
// wmma bf16-split GEMM core. CTA tile 128x128, 8 warps (4M x 2N),
// warp tile 32x64, BK=32, cp.async 3-stage pipeline, PAD=40 rows.
// ---------------------------------------------------------------------------
#define PAD 40
#define BKW 32
#define TILE_ELE (128*PAD)              // 5120 bf16 per operand tile
#define STAGE_ELE (4*TILE_ELE)          // 20480 bf16 per stage
#define GSM_BYTES (3*STAGE_ELE*2)       // 122880 bytes (3 stages)

// Mainloop macro: computes acc[2][4] for the CTA tile at (brow, bcol).
#define GEMM_MAINLOOP()                                                           \
    wmma::fragment<wmma::accumulator,16,16,16,float> acc[2][4];                   \
    _Pragma("unroll")                                                             \
    for (int i = 0; i < 2; i++)                                                   \
        _Pragma("unroll")                                                         \
        for (int j = 0; j < 4; j++) wmma::fill_fragment(acc[i][j], 0.f);          \
    int nsteps = K / BKW;                                                         \
    auto load_stage = [&](int ks, int buf) {                                      \
        _Pragma("unroll")                                                         \
        for (int it = 0; it < 8; it++) {                                          \
            int t  = tid + it*256;                                                \
            int op = t >> 9;                                                      \
            int r  = (t >> 2) & 127;                                              \
            int ch = t & 3;                                                       \
            const __nv_bfloat16* g;                                               \
            if (op == 0)      g = Ahi + (size_t)(brow + r)*K + ks*BKW + ch*8;     \
            else if (op == 1) g = Alo + (size_t)(brow + r)*K + ks*BKW + ch*8;     \
            else if (op == 2) g = Bhi + (size_t)(bcol + r)*K + ks*BKW + ch*8;     \
            else              g = Blo + (size_t)(bcol + r)*K + ks*BKW + ch*8;     \
            uint32_t s = smem_base +                                              \
                (uint32_t)(buf*STAGE_ELE + op*TILE_ELE + r*PAD + ch*8)*2u;        \
            asm volatile("cp.async.cg.shared.global [%0], [%1], 16;"              \
                         :: "r"(s), "l"(g));                                      \
        }                                                                         \
        asm volatile("cp.async.commit_group;");                                   \
    };                                                                            \
    load_stage(0, 0);                                                             \
    load_stage(1, 1);                                                             \
    for (int ks = 0; ks < nsteps; ks++) {                                         \
        asm volatile("cp.async.wait_group 1;");                                   \
        __syncthreads();                                                          \
        if (ks + 2 < nsteps) load_stage(ks + 2, (ks + 2) % 3);                    \
        else asm volatile("cp.async.commit_group;");                              \
        const __nv_bfloat16* sA_hi = smb + (ks % 3)*STAGE_ELE;                    \
        const __nv_bfloat16* sA_lo = sA_hi + TILE_ELE;                            \
        const __nv_bfloat16* sB_hi = sA_hi + 2*TILE_ELE;                          \
        const __nv_bfloat16* sB_lo = sA_hi + 3*TILE_ELE;                          \
        _Pragma("unroll")                                                         \
        for (int kk = 0; kk < 2; kk++) {                                          \
            wmma::fragment<wmma::matrix_a,16,16,16,__nv_bfloat16,                 \
                           wmma::row_major> ah[2], al[2];                         \
            wmma::fragment<wmma::matrix_b,16,16,16,__nv_bfloat16,                 \
                           wmma::col_major> bh[4], bl[4];                         \
            _Pragma("unroll")                                                     \
            for (int mi = 0; mi < 2; mi++) {                                      \
                int m0 = warp_m*32 + mi*16;                                       \
                wmma::load_matrix_sync(ah[mi], sA_hi + m0*PAD + kk*16, PAD);      \
                wmma::load_matrix_sync(al[mi], sA_lo + m0*PAD + kk*16, PAD);      \
            }                                                                     \
            _Pragma("unroll")                                                     \
            for (int ni = 0; ni < 4; ni++) {                                      \
                int n0 = warp_n*64 + ni*16;                                       \
                wmma::load_matrix_sync(bh[ni], sB_hi + n0*PAD + kk*16, PAD);      \
                wmma::load_matrix_sync(bl[ni], sB_lo + n0*PAD + kk*16, PAD);      \
            }                                                                     \
            _Pragma("unroll")                                                     \
            for (int mi = 0; mi < 2; mi++)                                        \
                _Pragma("unroll")                                                 \
                for (int ni = 0; ni < 4; ni++) {                                  \
                    wmma::mma_sync(acc[mi][ni], ah[mi], bh[ni], acc[mi][ni]);     \
                    wmma::mma_sync(acc[mi][ni], ah[mi], bl[ni], acc[mi][ni]);     \
                    wmma::mma_sync(acc[mi][ni], al[mi], bh[ni], acc[mi][ni]);     \
                }                                                                 \
        }                                                                         \
    }                                                                             \
    asm volatile("cp.async.wait_group 0;");                                       \
    __syncthreads();                                                              \
    float* sep = (float*)smb;                                                     \
    _Pragma("unroll")                                                             \
    for (int mi = 0; mi < 2; mi++)                                                \
        _Pragma("unroll")                                                         \
        for (int ni = 0; ni < 4; ni++)                                            \
            wmma::store_matrix_sync(                                              \
                sep + (warp_m*32 + mi*16)*132 + warp_n*64 + ni*16,                \
                acc[mi][ni], 132, wmma::mem_row_major);                           \
    __syncthreads();

// Generic GEMM: out[M,N] = (A.B^T + bias)*scale (+ add)
__global__ __launch_bounds__(256, 1) void gemm_wmma_kernel(
        const __nv_bfloat16* __restrict__ Ahi, const __nv_bfloat16* __restrict__ Alo,
        const __nv_bfloat16* __restrict__ Bhi, const __nv_bfloat16* __restrict__ Blo,
        const float* __restrict__ bias, const float* add, float* __restrict__ out,
        int M, int N, int K, float scale) {
    extern __shared__ __nv_bfloat16 smb[];
    int tid = threadIdx.x, wid = tid >> 5;
    int brow = blockIdx.y * 128;
    int bcol = blockIdx.x * 128;
    int warp_m = wid & 3;
    int warp_n = wid >> 2;
    uint32_t smem_base = smem_u32(smb);
    GEMM_MAINLOOP();
    for (int t = tid; t < 128*128; t += 256) {
        int r = t >> 7, c = t & 127;
        int m = brow + r, n = bcol + c;
        float v = (sep[r*132 + c] + bias[n]) * scale;
        if (add) v += add[(size_t)m*N + n];
        out[(size_t)m*N + n] = v;
    }
}

// Fused QKV GEMM: B = concat(q_w,k_w,v_w) as [3072,K]; routes outputs.
__global__ __launch_bounds__(256, 1) void gemm_qkv_kernel(
        const __nv_bfloat16* __restrict__ Ahi, const __nv_bfloat16* __restrict__ Alo,
        const __nv_bfloat16* __restrict__ Bhi, const __nv_bfloat16* __restrict__ Blo,
        const float* __restrict__ bq, const float* __restrict__ bk,
        const float* __restrict__ bv,
        float* __restrict__ oq, float* __restrict__ ok, float* __restrict__ ov,
        int M, int K) {
    extern __shared__ __nv_bfloat16 smb[];
    int tid = threadIdx.x, wid = tid >> 5;
    int brow = blockIdx.y * 128;
    int bcol = blockIdx.x * 128;           // in [0, 3072)
    int warp_m = wid & 3;
    int warp_n = wid >> 2;
    uint32_t smem_base = smem_u32(smb);
    GEMM_MAINLOOP();
    int op = bcol >> 10;                   // tile fully inside one operand
    const float* bias = (op == 0) ? bq : (op == 1) ? bk : bv;
    float* out = (op == 0) ? oq : (op == 1) ? ok : ov;
    float scale = (op == 1) ? SCALE_K : 1.0f;
    int ncol0 = bcol & 1023;
    for (int t = tid; t < 128*128; t += 256) {
        int r = t >> 7, c = t & 127;
        int m = brow + r, n = ncol0 + c;
        out[(size_t)m*C + n] = (sep[r*132 + c] + bias[n]) * scale;
    }
}

// ---------------------------------------------------------------------------
// RoPE-like table init
// ---------------------------------------------------------------------------
__global__ void rope_init_kernel() {
    int idx = blockIdx.x*blockDim.x + threadIdx.x;
    if (idx >= NPATCH*KD) return;
    int pos = idx >> 6;
    int d   = idx & 63;
    float t = (float)(d >> 1) / 31.0f;
    float ang = powf(10000.0f, -t);
    float a = (float)pos * ang;
    g_sin[idx] = sinf(a);
    g_cos[idx] = cosf(a);
}

__global__ void copy_in_kernel(const float* __restrict__ x) {
    int idx = blockIdx.x*blockDim.x + threadIdx.x;
    if (idx >= M_ROWS*C) return;
    int m = idx >> 10;
    int c = idx & 1023;
    int b = m / NPATCH;
    int p = m % NPATCH;
    g_patch[idx] = x[((size_t)b*(NPATCH+1) + 1 + p)*C + c];
}

__global__ void write_out_kernel(const float* __restrict__ x, float* __restrict__ out) {
    int idx = blockIdx.x*blockDim.x + threadIdx.x;
    if (idx >= BATCH*(NPATCH+1)*C) return;
    int row = idx >> 10;
    int c   = idx & 1023;
    int b = row / (NPATCH+1);
    int r = row % (NPATCH+1);
    out[idx] = (r == 0) ? x[idx] : g_patch[((size_t)(b*NPATCH + r - 1))*C + c];
}

// ---------------------------------------------------------------------------
// LayerNorm over C=1024 -> bf16 hi/lo (GEMM operand) directly.
// ---------------------------------------------------------------------------
__global__ __launch_bounds__(256) void ln_bf_kernel(const float* __restrict__ src,
                                                    const float* __restrict__ w,
                                                    const float* __restrict__ b,
                                                    __nv_bfloat16* __restrict__ hi,
                                                    __nv_bfloat16* __restrict__ lo) {
    __shared__ float row[C];
    __shared__ float red[256];
    int r = blockIdx.x;
    const float* xr = src + (size_t)r*C;
    float s = 0.f;
    for (int c = threadIdx.x; c < C; c += 256) { float v = xr[c]; row[c] = v; s += v; }
    red[threadIdx.x] = s; __syncthreads();
    for (int off = 128; off > 0; off >>= 1) {
        if (threadIdx.x < off) red[threadIdx.x] += red[threadIdx.x+off];
        __syncthreads();
    }
    float mean = red[0] * (1.0f/C);
    __syncthreads();
    float s2 = 0.f;
    for (int c = threadIdx.x; c < C; c += 256) { float d = row[c]-mean; s2 += d*d; }
    red[threadIdx.x] = s2; __syncthreads();
    for (int off = 128; off > 0; off >>= 1) {
        if (threadIdx.x < off) red[threadIdx.x] += red[threadIdx.x+off];
        __syncthreads();
    }
    float rstd = rsqrtf(red[0]*(1.0f/C) + 1e-5f);
    for (int c = threadIdx.x; c < C; c += 256) {
        float v = (row[c]-mean)*rstd*w[c] + b[c];
        __nv_bfloat16 h, l; split_bf(v, h, l);
        hi[(size_t)r*C + c] = h;
        lo[(size_t)r*C + c] = l;
    }
}

// ---------------------------------------------------------------------------
// Theta shift (in place, q AND k)
// ---------------------------------------------------------------------------
__global__ void theta_shift_kernel(float* __restrict__ q, float* __restrict__ k) {
    int idx = blockIdx.x*blockDim.x + threadIdx.x;
    if (idx >= M_ROWS*(C/2)) return;
    int m  = idx >> 9;
    int p  = idx & 511;
    int c0 = p*2;
    int d0 = c0 & 63;
    int pos = m % NPATCH;
    size_t base = (size_t)m*C + c0;
    float s0 = g_sin[pos*KD + d0],   cv0 = g_cos[pos*KD + d0];
    float s1 = g_sin[pos*KD + d0+1], cv1 = g_cos[pos*KD + d0+1];
    float q1 = q[base], q2 = q[base+1];
    q[base]   = q1*cv0 - q2*s0;
    q[base+1] = q2*cv1 + q1*s1;
    float k1 = k[base], k2 = k[base+1];
    k[base]   = k1*cv0 - k2*s0;
    k[base+1] = k2*cv1 + k1*s1;
}

// ---------------------------------------------------------------------------
// Axial attention pass 1 (along width)
// ---------------------------------------------------------------------------
__global__ __launch_bounds__(256) void attn_w_kernel(const float* __restrict__ q,
                                                     const float* __restrict__ k,
                                                     const float* __restrict__ v,
                                                     float* __restrict__ out) {
    int bid = blockIdx.x;
    int h = bid % HS;
    int n = (bid / HS) % NH;
    int b = bid / (HS*NH);
    __shared__ float qs[HS][KD], ks[HS][KD], vs[HS][KD];
    __shared__ float sc[HS][HS];
    int baserow = b*NPATCH + h*HS;
    int col = n*KD;
    for (int t = threadIdx.x; t < HS*KD; t += 256) {
        int w = t >> 6, d = t & 63;
        size_t off = (size_t)(baserow + w)*C + col + d;
        qs[w][d] = q[off]; ks[w][d] = k[off]; vs[w][d] = v[off];
    }
    __syncthreads();
    float decay = logf(1.0f - exp2f(-1.0f - (float)n));
    for (int t = threadIdx.x; t < HS*HS; t += 256) {
        int w = t / HS, u = t % HS;
        float s = 0.f;
        #pragma unroll
        for (int d = 0; d < KD; d++) s = fmaf(qs[w][d], ks[u][d], s);
        sc[w][u] = s + fabsf((float)(w-u)) * decay;
    }
    __syncthreads();
    if (threadIdx.x < HS) {
        int w = threadIdx.x;
        float mx = -1e30f;
        for (int u = 0; u < HS; u++) mx = fmaxf(mx, sc[w][u]);
        float sum = 0.f, e[HS];
        for (int u = 0; u < HS; u++) { e[u] = __expf(sc[w][u]-mx); sum += e[u]; }
        float inv = 1.0f/sum;
        for (int u = 0; u < HS; u++) sc[w][u] = e[u]*inv;
    }
    __syncthreads();
    for (int t = threadIdx.x; t < HS*KD; t += 256) {
        int w = t >> 6, d = t & 63;
        float o = 0.f;
        #pragma unroll
        for (int u = 0; u < HS; u++) o = fmaf(sc[w][u], vs[u][d], o);
        out[(size_t)(baserow + w)*C + col + d] = o;
    }
}

// ---------------------------------------------------------------------------
// Axial attention pass 2 (along height)
// ---------------------------------------------------------------------------
__global__ __launch_bounds__(256) void attn_h_kernel(const float* __restrict__ q,
                                                     const float* __restrict__ k,
                                                     const float* __restrict__ v,
                                                     float* __restrict__ out) {
    int bid = blockIdx.x;
    int w = bid % HS;
    int n = (bid / HS) % NH;
    int b = bid / (HS*NH);
    __shared__ float qs[HS][KD], ks[HS][KD], vs[HS][KD];
    __shared__ float sc[HS][HS];
    int col = n*KD;
    for (int t = threadIdx.x; t < HS*KD; t += 256) {
        int hh = t >> 6, d = t & 63;
        size_t off = (size_t)(b*NPATCH + hh*HS + w)*C + col + d;
        qs[hh][d] = q[off]; ks[hh][d] = k[off]; vs[hh][d] = v[off];
    }
    __syncthreads();
    float decay = logf(1.0f - exp2f(-1.0f - (float)n));
    for (int t = threadIdx.x; t < HS*HS; t += 256) {
        int hh = t / HS, u = t % HS;
        float s = 0.f;
        #pragma unroll
        for (int d = 0; d < KD; d++) s = fmaf(qs[hh][d], ks[u][d], s);
        sc[hh][u] = s + fabsf((float)(hh-u)) * decay;
    }
    __syncthreads();
    if (threadIdx.x < HS) {
        int hh = threadIdx.x;
        float mx = -1e30f;
        for (int u = 0; u < HS; u++) mx = fmaxf(mx, sc[hh][u]);
        float sum = 0.f, e[HS];
        for (int u = 0; u < HS; u++) { e[u] = __expf(sc[hh][u]-mx); sum += e[u]; }
        float inv = 1.0f/sum;
        for (int u = 0; u < HS; u++) sc[hh][u] = e[u]*inv;
    }
    __syncthreads();
    for (int t = threadIdx.x; t < HS*KD; t += 256) {
        int hh = t >> 6, d = t & 63;
        float o = 0.f;
        #pragma unroll
        for (int u = 0; u < HS; u++) o = fmaf(sc[hh][u], vs[u][d], o);
        out[(size_t)(b*NPATCH + hh*HS + w)*C + col + d] = o;
    }
}

// ---------------------------------------------------------------------------
// LePE + attention residual: val = attn[idx] + dwconv5(v) + bias -> bf16 hi/lo
// ---------------------------------------------------------------------------
__global__ void lepe_bf_kernel(const float* __restrict__ v,
                               const float* __restrict__ attn,
                               const float* __restrict__ wgt,
                               const float* __restrict__ bias,
                               __nv_bfloat16* __restrict__ hi,
                               __nv_bfloat16* __restrict__ lo) {
    int idx = blockIdx.x*blockDim.x + threadIdx.x;
    if (idx >= M_ROWS*C) return;
    int c = idx & 1023;
    int m = idx >> 10;
    int b = m / NPATCH;
    int p = m % NPATCH;
    int h = p / HS, w0 = p % HS;
    float acc = bias[c];
    #pragma unroll
    for (int kh = 0; kh < 5; kh++) {
        int hh = h + kh - 2;
        if (hh < 0 || hh >= HS) continue;
        #pragma unroll
        for (int kw = 0; kw < 5; kw++) {
            int ww = w0 + kw - 2;
            if (ww < 0 || ww >= HS) continue;
            acc = fmaf(v[(size_t)(b*NPATCH + hh*HS + ww)*C + c],
                       wgt[(kh*5+kw)*C + c], acc);
        }
    }
    float val = attn[idx] + acc;
    __nv_bfloat16 h16, l16; split_bf(val, h16, l16);
    hi[idx] = h16;
    lo[idx] = l16;
}

// ---------------------------------------------------------------------------
// DyT: tanh(alpha*x)*w + b -> bf16 hi/lo (GEMM operand)
// ---------------------------------------------------------------------------
__global__ void dyt_bf_kernel(const float* __restrict__ hbuf,
                              const float* __restrict__ alpha,
                              const float* __restrict__ w,
                              const float* __restrict__ b,
                              __nv_bfloat16* __restrict__ hi,
                              __nv_bfloat16* __restrict__ lo) {
    int idx = blockIdx.x*blockDim.x + threadIdx.x;
    if (idx >= M_ROWS*HID) return;
    int c = idx & 4095;
    float v = tanhf(alpha[0]*hbuf[idx])*w[c] + b[c];
    __nv_bfloat16 h, l; split_bf(v, h, l);
    hi[idx] = h;
    lo[idx] = l;
}

// ---------------------------------------------------------------------------
// Launch
// ---------------------------------------------------------------------------
static void cvt(const float* src, __nv_bfloat16* hi, __nv_bfloat16* lo, int n) {
    int n4 = n / 4;
    cvt_split_kernel<<<(n4+255)/256, 256>>>((const float4*)src,
                                            (__nv_bfloat162*)hi, (__nv_bfloat162*)lo, n4);
}

extern "C" void kernel_launch(void* const* d_in, const int* in_sizes, int n_in,
                              void* d_out, int out_size) {
    const float* x      = (const float*)d_in[0];
    const float* ln1_w  = (const float*)d_in[1];
    const float* ln1_b  = (const float*)d_in[2];
    const float* q_w    = (const float*)d_in[3];
    const float* q_b    = (const float*)d_in[4];
    const float* k_w    = (const float*)d_in[5];
    const float* k_b    = (const float*)d_in[6];
    const float* v_w    = (const float*)d_in[7];
    const float* v_b    = (const float*)d_in[8];
    const float* lepe_w = (const float*)d_in[9];
    const float* lepe_b = (const float*)d_in[10];
    const float* out_w  = (const float*)d_in[11];
    const float* out_b  = (const float*)d_in[12];
    const float* ln2_w  = (const float*)d_in[13];
    const float* ln2_b  = (const float*)d_in[14];
    const float* fc1_w  = (const float*)d_in[15];
    const float* fc1_b  = (const float*)d_in[16];
    const float* alpha  = (const float*)d_in[17];
    const float* dyt_w  = (const float*)d_in[18];
    const float* dyt_b  = (const float*)d_in[19];
    const float* fc2_w  = (const float*)d_in[20];
    const float* fc2_b  = (const float*)d_in[21];
    float* out = (float*)d_out;

    float *patch, *xn, *qb, *kb, *vb, *hid;
    __nv_bfloat16 *ahi, *alo, *bhi, *blo;
    cudaGetSymbolAddress((void**)&patch, g_patch);
    cudaGetSymbolAddress((void**)&xn,    g_xn);
    cudaGetSymbolAddress((void**)&qb,    g_q);
    cudaGetSymbolAddress((void**)&kb,    g_k);
    cudaGetSymbolAddress((void**)&vb,    g_v);
    cudaGetSymbolAddress((void**)&hid,   g_hid);
    cudaGetSymbolAddress((void**)&ahi,   g_ahi);
    cudaGetSymbolAddress((void**)&alo,   g_alo);
    cudaGetSymbolAddress((void**)&bhi,   g_bhi);
    cudaGetSymbolAddress((void**)&blo,   g_blo);

    cudaFuncSetAttribute(gemm_wmma_kernel, cudaFuncAttributeMaxDynamicSharedMemorySize, GSM_BYTES);
    cudaFuncSetAttribute(gemm_qkv_kernel,  cudaFuncAttributeMaxDynamicSharedMemorySize, GSM_BYTES);

    rope_init_kernel<<<(NPATCH*KD+255)/256, 256>>>();
    copy_in_kernel<<<(M_ROWS*C+255)/256, 256>>>(x);

    dim3 gC  (C/128,    M_ROWS/128);   // (8, 49)
    dim3 gQKV(3*C/128,  M_ROWS/128);   // (24, 49)
    dim3 gH  (HID/128,  M_ROWS/128);   // (32, 49)

    for (int d = 0; d < D_LAYERS; d++) {
        const float* l1w = ln1_w + d*C;   const float* l1b = ln1_b + d*C;
        const float* qw  = q_w  + (size_t)d*C*C;   const float* qbi = q_b  + d*C;
        const float* kw  = k_w  + (size_t)d*C*C;   const float* kbi = k_b  + d*C;
        const float* vw  = v_w  + (size_t)d*C*C;   const float* vbi = v_b  + d*C;
        const float* lw  = lepe_w + (size_t)d*25*C; const float* lb = lepe_b + d*C;
        const float* ow  = out_w + (size_t)d*C*C;  const float* obi = out_b + d*C;
        const float* l2w = ln2_w + d*C;   const float* l2b = ln2_b + d*C;
        const float* f1w = fc1_w + (size_t)d*HID*C; const float* f1b = fc1_b + d*HID;
        const float* al  = alpha + d;
        const float* dw  = dyt_w + d*HID; const float* db = dyt_b + d*HID;
        const float* f2w = fc2_w + (size_t)d*C*HID; const float* f2b = fc2_b + d*C;

        // --- attention half ---
        ln_bf_kernel<<<M_ROWS, 256>>>(patch, l1w, l1b, ahi, alo);
        cvt(qw, bhi,         blo,         C*C);
        cvt(kw, bhi + C*C,   blo + C*C,   C*C);
        cvt(vw, bhi + 2*C*C, blo + 2*C*C, C*C);
        gemm_qkv_kernel<<<gQKV, 256, GSM_BYTES>>>(ahi, alo, bhi, blo,
                                                  qbi, kbi, vbi, qb, kb, vb,
                                                  M_ROWS, C);
        theta_shift_kernel<<<(M_ROWS*(C/2)+255)/256, 256>>>(qb, kb);
        attn_w_kernel<<<BATCH*NH*HS, 256>>>(qb, kb, vb, hid);   // hid as temp
        attn_h_kernel<<<BATCH*NH*HS, 256>>>(qb, kb, hid, xn);
        lepe_bf_kernel<<<(M_ROWS*C+255)/256, 256>>>(vb, xn, lw, lb, ahi, alo);
        cvt(ow, bhi, blo, C*C);
        gemm_wmma_kernel<<<gC, 256, GSM_BYTES>>>(ahi, alo, bhi, blo, obi, patch, patch,
                                                 M_ROWS, C, C, 1.0f);

        // --- MLP half ---
        ln_bf_kernel<<<M_ROWS, 256>>>(patch, l2w, l2b, ahi, alo);
        cvt(f1w, bhi, blo, HID*C);
        gemm_wmma_kernel<<<gH, 256, GSM_BYTES>>>(ahi, alo, bhi, blo, f1b, nullptr, hid,
                                                 M_ROWS, HID, C, 1.0f);
        dyt_bf_kernel<<<(M_ROWS*HID+255)/256, 256>>>(hid, al, dw, db, ahi, alo);
        cvt(f2w, bhi, blo, C*HID);
        gemm_wmma_kernel<<<gC, 256, GSM_BYTES>>>(ahi, alo, bhi, blo, f2b, patch, patch,
                                                 M_ROWS, C, HID, 1.0f);
    }

    write_out_kernel<<<(BATCH*(NPATCH+1)*C+255)/256, 256>>>(x, out);
}